// round 1
// baseline (speedup 1.0000x reference)
#include <cuda_runtime.h>
#include <cuda_bf16.h>
#include <math.h>

// Problem constants (fixed by setup_inputs)
#define V_N   20000
#define D_K   256
#define NHEAD 4
#define O_DIM 128
#define NCOL  512   // NHEAD * O_DIM
#define KNBR  16

// ---------------- scratch (no allocations allowed) ----------------
__device__ float g_t[(size_t)V_N * NCOL];     // t concat over heads: [V, H*O], 41 MB
__device__ float g_attn[NHEAD * V_N];          // attn[h*V + v]
__device__ float g_wa[NHEAD * D_K];            // wa[h*D + d] = sum_o W[h,d,o]*a[h,o]
__device__ int   g_adj64;                      // 1 if adj_lst is int64, 0 if int32

// ---------------- adj dtype detection ----------------
__global__ void detect_adj_kernel(const void* __restrict__ adj) {
    // If the data were int32, reading pairs as int64 yields values with a
    // (almost surely) nonzero high word -> out of [0, V] range.
    const long long* p = (const long long*)adj;
    int ok = 1;
    for (int i = 0; i < 64; i++) {
        long long v = p[i];
        if (v < 0 || v > (long long)V_N) { ok = 0; break; }
    }
    g_adj64 = ok;
}

// ---------------- wa[h,d] = sum_o W[h,d,o] * a[h,o] ----------------
__global__ void wa_kernel(const float* __restrict__ W, const float* __restrict__ a) {
    int h = blockIdx.x;
    int d = threadIdx.x;            // 256 threads
    const float* Wd = W + ((size_t)h * D_K + d) * O_DIM;
    const float* ah = a + h * O_DIM;
    float s = 0.f;
    #pragma unroll 8
    for (int o = 0; o < O_DIM; o++) s += Wd[o] * ah[o];
    g_wa[h * D_K + d] = s;
}

// ---------------- attn[h,v] = x[v] . wa[h] ----------------
__global__ __launch_bounds__(128) void attn_kernel(const float* __restrict__ x) {
    int v = blockIdx.x;
    __shared__ float sx[D_K];
    int tid = threadIdx.x;
    const float* xr = x + (size_t)v * D_K;
    sx[tid]       = xr[tid];
    sx[tid + 128] = xr[tid + 128];
    __syncthreads();
    int w = tid >> 5;   // head
    int l = tid & 31;
    const float* wah = g_wa + w * D_K;
    float s = 0.f;
    #pragma unroll
    for (int j = 0; j < 8; j++) {
        int d = l + j * 32;
        s += sx[d] * wah[d];
    }
    #pragma unroll
    for (int off = 16; off; off >>= 1) s += __shfl_xor_sync(0xffffffffu, s, off);
    if (l == 0) g_attn[w * V_N + v] = s;
}

// ---------------- GEMM: g_t[v, h*O+o] = sum_d x[v,d] * W[h,d,o] ----------------
// Register-tiled fp32 SIMT GEMM. BM=128, BN=64, BK=16, TM=8, TN=4, 256 threads.
#define BM 128
#define BN 64
#define BK 16
#define TM 8
#define TN 4

__global__ __launch_bounds__(256) void gemm_kernel(const float* __restrict__ x,
                                                   const float* __restrict__ W) {
    __shared__ float As[BK][BM];   // transposed A tile
    __shared__ float Bs[BK][BN];

    int tid = threadIdx.x;
    int tx = tid & 15;             // m direction (16 groups of 8 rows)
    int ty = tid >> 4;             // n direction (16 groups of 4 cols)
    int m0 = blockIdx.x * BM;
    int n0 = blockIdx.y * BN;      // global column base within [0, 512)
    int head = n0 >> 7;            // which head
    int o0   = n0 & 127;           // column offset within the head (0 or 64)

    // A-load mapping: each thread loads 2x float4
    int arow  = tid >> 2;          // 0..63
    int acol4 = tid & 3;           // k-offset group
    // B-load mapping: one float4 per thread
    int brow  = tid >> 4;          // 0..15 (k within tile)
    int bcol4 = tid & 15;          // 0..15 (col group)

    const float* Wh = W + (size_t)head * D_K * O_DIM + o0;  // W[head][d][o0 + ...]

    float acc[TM][TN];
    #pragma unroll
    for (int i = 0; i < TM; i++)
        #pragma unroll
        for (int j = 0; j < TN; j++) acc[i][j] = 0.f;

    for (int kt = 0; kt < D_K; kt += BK) {
        // ---- load A tile (transposed into smem) ----
        #pragma unroll
        for (int i = 0; i < 2; i++) {
            int r  = arow + i * 64;
            int gm = m0 + r;
            float4 vq = make_float4(0.f, 0.f, 0.f, 0.f);
            if (gm < V_N)
                vq = *(const float4*)(x + (size_t)gm * D_K + kt + acol4 * 4);
            As[acol4 * 4 + 0][r] = vq.x;
            As[acol4 * 4 + 1][r] = vq.y;
            As[acol4 * 4 + 2][r] = vq.z;
            As[acol4 * 4 + 3][r] = vq.w;
        }
        // ---- load B tile ----
        {
            float4 bq = *(const float4*)(Wh + (size_t)(kt + brow) * O_DIM + bcol4 * 4);
            *(float4*)&Bs[brow][bcol4 * 4] = bq;
        }
        __syncthreads();

        #pragma unroll
        for (int kk = 0; kk < BK; kk++) {
            float4 a0 = *(const float4*)&As[kk][tx * TM];
            float4 a1 = *(const float4*)&As[kk][tx * TM + 4];
            float4 bq = *(const float4*)&Bs[kk][ty * TN];
            float af[TM] = {a0.x, a0.y, a0.z, a0.w, a1.x, a1.y, a1.z, a1.w};
            float bf[TN] = {bq.x, bq.y, bq.z, bq.w};
            #pragma unroll
            for (int i = 0; i < TM; i++)
                #pragma unroll
                for (int j = 0; j < TN; j++)
                    acc[i][j] = fmaf(af[i], bf[j], acc[i][j]);
        }
        __syncthreads();
    }

    // ---- store ----
    #pragma unroll
    for (int i = 0; i < TM; i++) {
        int row = m0 + tx * TM + i;
        if (row < V_N) {
            float4 o4 = make_float4(acc[i][0], acc[i][1], acc[i][2], acc[i][3]);
            *(float4*)(g_t + (size_t)row * NCOL + n0 + ty * TN) = o4;
        }
    }
}

// ---------------- aggregation: softmax over neighbors + weighted sum ----------------
__global__ __launch_bounds__(128) void aggregate_kernel(const void* __restrict__ adj,
                                                        const float* __restrict__ b,
                                                        float* __restrict__ out) {
    int v   = blockIdx.x;
    int tid = threadIdx.x;

    __shared__ float s_score[NHEAD][KNBR];  // scores, then exp values
    __shared__ float s_coef [NHEAD][KNBR];
    __shared__ int   s_idx  [NHEAD][KNBR];

    if (tid < NHEAD * KNBR) {
        int h = tid >> 4;
        int k = tid & 15;
        long long a;
        if (g_adj64) a = ((const long long*)adj)[(size_t)v * KNBR + k];
        else         a = (long long)((const int*)adj)[(size_t)v * KNBR + k];
        bool pad = (a >= (long long)V_N) || (a < 0);
        int n = pad ? -1 : (int)a;
        s_idx[h][k]   = n;
        s_score[h][k] = pad ? -1e9f : g_attn[h * V_N + n];
    }
    __syncthreads();

    if (tid < NHEAD) {
        float mx = -INFINITY;
        #pragma unroll
        for (int k = 0; k < KNBR; k++) mx = fmaxf(mx, s_score[tid][k]);
        float s = 0.f;
        #pragma unroll
        for (int k = 0; k < KNBR; k++) {
            float e = expf(s_score[tid][k] - mx);
            s_score[tid][k] = e;
            s += e;
        }
        float inv = 1.0f / s;
        #pragma unroll
        for (int k = 0; k < KNBR; k++) s_coef[tid][k] = s_score[tid][k] * inv;
    }
    __syncthreads();

    int o = tid;  // 128 threads = O_DIM
    float acc = 0.f;
    #pragma unroll
    for (int h = 0; h < NHEAD; h++) {
        const float* th = g_t + h * O_DIM + o;
        float ah = 0.f;
        #pragma unroll
        for (int k = 0; k < KNBR; k++) {
            int   n = s_idx[h][k];
            float c = s_coef[h][k];
            if (n >= 0) ah = fmaf(c, __ldg(th + (size_t)n * NCOL), ah);
        }
        acc += ah;
    }
    float bm = 0.25f * (b[o] + b[O_DIM + o] + b[2 * O_DIM + o] + b[3 * O_DIM + o]);
    float r  = fmaf(acc, 0.25f, bm);
    out[(size_t)v * O_DIM + o] = fmaxf(r, 0.f);
}

// ---------------- launch ----------------
extern "C" void kernel_launch(void* const* d_in, const int* in_sizes, int n_in,
                              void* d_out, int out_size) {
    const float* x   = (const float*)d_in[0];   // [V, D]
    const float* W   = (const float*)d_in[1];   // [H, D, O]
    const float* a   = (const float*)d_in[2];   // [H, O]
    const float* b   = (const float*)d_in[3];   // [H, O]
    const void*  adj = d_in[4];                 // [V, K] int32 or int64
    float* out = (float*)d_out;                 // [V, O]

    detect_adj_kernel<<<1, 1>>>(adj);
    wa_kernel<<<NHEAD, 256>>>(W, a);
    attn_kernel<<<V_N, 128>>>(x);
    dim3 ggrid((V_N + BM - 1) / BM, NCOL / BN);
    gemm_kernel<<<ggrid, 256>>>(x, W);
    aggregate_kernel<<<V_N, 128>>>(adj, b, out);
}